// round 8
// baseline (speedup 1.0000x reference)
#include <cuda_runtime.h>
#include <math.h>

// Problem constants
#define MROWS 81920          // BV*HW = 20*4096  (== B*L = 4*20480)
#define CDIM  256
#define LB    20480          // rows per batch n
#define HN    8
#define DH    32
#define NBATCH 4
#define TILES 160            // L-tiles of 128 per batch
#define TM 128

// Scratch (static __device__ — no allocation allowed)
__device__ float g_q   [MROWS * CDIM];                  // elu(q)+1
__device__ float g_z   [MROWS * HN];                    // per-(row,head) 1/(q.ksum+eps)
__device__ float g_kvp [(long)640 * HN * DH * DH];      // per-tile kv partials
__device__ float g_ksp [(long)640 * HN * DH];           // per-tile k_sum partials
__device__ float g_ksum[NBATCH * CDIM];                 // [n][h*32+d]
__device__ float g_P   [NBATCH * CDIM * CDIM];          // P_n = kv^T @ W_proj

__device__ __forceinline__ unsigned f2tf(float f) {
    unsigned u;
    asm("cvt.rna.tf32.f32 %0, %1;" : "=r"(u) : "f"(f));
    return u;
}

__device__ __forceinline__ void mma_tf32(float* c, const unsigned* a, const unsigned* b) {
    asm volatile(
        "mma.sync.aligned.m16n8k8.row.col.f32.tf32.tf32.f32 "
        "{%0,%1,%2,%3}, {%4,%5,%6,%7}, {%8,%9}, {%0,%1,%2,%3};\n"
        : "+f"(c[0]), "+f"(c[1]), "+f"(c[2]), "+f"(c[3])
        : "r"(a[0]), "r"(a[1]), "r"(a[2]), "r"(a[3]), "r"(b[0]), "r"(b[1]));
}

// k1 smem word offsets
#define K1_A    0            // [128][260] tf32 (resident x tile)
#define K1_B    33280        // 2 x [32][104] tf32 (W chunk, double buf)
#define K1_PL   39936        // 4 planes [32][132]: khi, vhi, klo, vlo
#define K1_TOT  56832        // words -> 227328 bytes

// ---------------------------------------------------------------------------
// k1: per L-tile of 128 rows, ALL heads: resident A, streamed W chunks,
//     TF32 MMA qkv; elu+1; q->g_q; kv via compensated TF32 MMA; ksum.
// ---------------------------------------------------------------------------
__device__ __forceinline__ void k1_loadB(unsigned* Bb, const float* __restrict__ Wqkv,
                                         int h, int kb, int tid)
{
    #pragma unroll
    for (int it = 0; it < 2; ++it) {
        int idx = tid + it * 512;              // 0..1023, need 768
        if (it == 1 && idx >= 768) break;
        int r = idx / 24, c4 = idx % 24;
        int j = c4 * 4;
        int part = j >> 5, jj = j & 31;
        float4 v = *(const float4*)(Wqkv + (kb * 32 + r) * 768 + part * 256 + h * 32 + jj);
        uint4 u = { f2tf(v.x), f2tf(v.y), f2tf(v.z), f2tf(v.w) };
        *(uint4*)&Bb[r * 104 + j] = u;
    }
}

__global__ __launch_bounds__(512, 1) void k1_qkv(const float* __restrict__ x,
                                                 const float* __restrict__ Wqkv)
{
    extern __shared__ float sm[];
    unsigned* As  = (unsigned*)(sm + K1_A);
    unsigned* Bs  = (unsigned*)(sm + K1_B);
    unsigned* khi = (unsigned*)(sm + K1_PL);
    unsigned* vhi = khi + 4224;
    unsigned* klo = vhi + 4224;
    unsigned* vlo = klo + 4224;
    float* sc_kv = sm + K1_B;            // scratch (reuses B bufs, 1024 fl)
    float* sc_ks = sm + K1_B + 1024;     // 512 fl

    const int tile = blockIdx.x;         // 0..639
    const int tid  = threadIdx.x;
    const int warp = tid >> 5, lane = tid & 31;
    const int wm = warp >> 2, wn = warp & 3;   // 4 x 4 warp grid
    const int rb = wm * 32, cb = wn * 24;      // warp tile 32 x 24
    const int g  = lane >> 2, tg = lane & 3;
    const long mbase = (long)tile * TM;

    // Resident A: 128 x 256 of x, tf32, row-major stride 260
    #pragma unroll
    for (int it = 0; it < 16; ++it) {
        int idx = tid + it * 512;              // 0..8191 float4s
        int r = idx >> 6, c4 = idx & 63;
        float4 v = *(const float4*)(x + (mbase + r) * CDIM + c4 * 4);
        uint4 u = { f2tf(v.x), f2tf(v.y), f2tf(v.z), f2tf(v.w) };
        *(uint4*)&As[r * 260 + c4 * 4] = u;
    }

    for (int h = 0; h < HN; ++h) {
        k1_loadB(Bs, Wqkv, h, 0, tid);
        __syncthreads();

        float acc[2][3][4];
        #pragma unroll
        for (int mt = 0; mt < 2; mt++)
            #pragma unroll
            for (int nt = 0; nt < 3; nt++)
                #pragma unroll
                for (int e = 0; e < 4; e++) acc[mt][nt][e] = 0.f;

        for (int kb = 0; kb < 8; ++kb) {
            int cur = kb & 1;
            if (kb < 7) k1_loadB(Bs + (cur ^ 1) * 3328, Wqkv, h, kb + 1, tid);
            unsigned* Bc = Bs + cur * 3328;
            #pragma unroll
            for (int ksl = 0; ksl < 32; ksl += 8) {
                unsigned a[2][4], b[3][2];
                #pragma unroll
                for (int mt = 0; mt < 2; mt++) {
                    int base = (rb + mt * 16 + g) * 260 + kb * 32 + ksl + tg;
                    a[mt][0] = As[base];
                    a[mt][1] = As[base + 8 * 260];
                    a[mt][2] = As[base + 4];
                    a[mt][3] = As[base + 8 * 260 + 4];
                }
                #pragma unroll
                for (int nt = 0; nt < 3; nt++) {
                    int col = cb + nt * 8 + g;
                    b[nt][0] = Bc[(ksl + tg) * 104 + col];
                    b[nt][1] = Bc[(ksl + tg + 4) * 104 + col];
                }
                #pragma unroll
                for (int mt = 0; mt < 2; mt++)
                    #pragma unroll
                    for (int nt = 0; nt < 3; nt++)
                        mma_tf32(acc[mt][nt], a[mt], b[nt]);
            }
            __syncthreads();
        }

        // Epilogue: elu+1 on q,k; q -> global; k,v hi/lo planes (transposed)
        #pragma unroll
        for (int mt = 0; mt < 2; mt++)
            #pragma unroll
            for (int nt = 0; nt < 3; nt++)
                #pragma unroll
                for (int e = 0; e < 4; e++) {
                    int r = rb + mt * 16 + g + ((e >= 2) ? 8 : 0);
                    int c = cb + nt * 8 + tg * 2 + (e & 1);
                    float val = acc[mt][nt][e];
                    int part = c >> 5, jj = c & 31;
                    if (part == 0) {
                        val = (val > 0.f) ? (val + 1.f) : expf(val);
                        g_q[(mbase + r) * CDIM + h * 32 + jj] = val;
                    } else if (part == 1) {
                        val = (val > 0.f) ? (val + 1.f) : expf(val);
                        unsigned hb = f2tf(val);
                        float hf = __uint_as_float(hb);
                        khi[jj * 132 + r] = hb;
                        klo[jj * 132 + r] = f2tf(val - hf);
                    } else {
                        unsigned hb = f2tf(val);
                        float hf = __uint_as_float(hb);
                        vhi[jj * 132 + r] = hb;
                        vlo[jj * 132 + r] = f2tf(val - hf);
                    }
                }
        __syncthreads();

        // kv[m][d] = sum_l v[l][m]*k[l][d] via compensated TF32 MMA
        {
            const int lh = warp >> 3;              // l-half
            const int sub = warp & 7;
            const int mh = sub & 1, no = sub >> 1; // m 16x2, d 8x4
            float c4v[4] = {0.f, 0.f, 0.f, 0.f};
            #pragma unroll
            for (int li = 0; li < 8; li++) {
                int l0 = lh * 64 + li * 8;
                unsigned avh[4], avl[4], bkh[2], bkl[2];
                int ab = (mh * 16 + g) * 132 + l0 + tg;
                avh[0] = vhi[ab];            avh[1] = vhi[ab + 8 * 132];
                avh[2] = vhi[ab + 4];        avh[3] = vhi[ab + 8 * 132 + 4];
                avl[0] = vlo[ab];            avl[1] = vlo[ab + 8 * 132];
                avl[2] = vlo[ab + 4];        avl[3] = vlo[ab + 8 * 132 + 4];
                int bb = (no * 8 + g) * 132 + l0 + tg;
                bkh[0] = khi[bb];            bkh[1] = khi[bb + 4];
                bkl[0] = klo[bb];            bkl[1] = klo[bb + 4];
                mma_tf32(c4v, avh, bkh);
                mma_tf32(c4v, avh, bkl);
                mma_tf32(c4v, avl, bkh);
            }
            // ksum partials (all threads): d = tid>>4, 16 l-chunks of 8
            {
                int d = tid >> 4, cc = tid & 15;
                float s = 0.f;
                #pragma unroll
                for (int l = cc * 8; l < cc * 8 + 8; l++)
                    s += __uint_as_float(khi[d * 132 + l]) +
                         __uint_as_float(klo[d * 132 + l]);
                sc_ks[d * 16 + cc] = s;
            }
            if (lh == 1) {
                #pragma unroll
                for (int e = 0; e < 4; e++)
                    sc_kv[(sub * 32 + lane) * 4 + e] = c4v[e];
            }
            __syncthreads();
            if (lh == 0) {
                #pragma unroll
                for (int e = 0; e < 4; e++) {
                    float s = c4v[e] + sc_kv[(sub * 32 + lane) * 4 + e];
                    int m  = mh * 16 + g + ((e >= 2) ? 8 : 0);
                    int d2 = no * 8 + tg * 2 + (e & 1);
                    g_kvp[(long)(tile * HN + h) * 1024 + m * 32 + d2] = s;
                }
            }
            if (tid < 32) {
                float s2 = 0.f;
                #pragma unroll
                for (int c = 0; c < 16; c++) s2 += sc_ks[tid * 16 + c];
                g_ksp[(long)(tile * HN + h) * 32 + tid] = s2;
            }
            __syncthreads();
        }
    }
}

// ---------------------------------------------------------------------------
// k_reduceP: fixed-order reduction of kv/k_sum partials per (n,h), then
//            P[n][h*32+d][j] = sum_m kv[m][d] * Wp[h*32+m][j]  (fp32 exact)
// ---------------------------------------------------------------------------
__global__ __launch_bounds__(1024) void k_reduceP(const float* __restrict__ Wp)
{
    __shared__ float kvs[1024];
    const int n = blockIdx.x, h = blockIdx.y;
    const int tid = threadIdx.x;  // 0..1023 (= m*32+d)
    float s = 0.f;
    for (int t = 0; t < TILES; t++)
        s += g_kvp[((long)(n * TILES + t) * HN + h) * 1024 + tid];
    kvs[tid] = s;
    if (tid < 32) {
        float s2 = 0.f;
        for (int t = 0; t < TILES; t++)
            s2 += g_ksp[((long)(n * TILES + t) * HN + h) * 32 + tid];
        g_ksum[n * CDIM + h * 32 + tid] = s2;
    }
    __syncthreads();

    const int j  = tid & 255;
    const int d0 = (tid >> 8) * 8;
    float w[32];
    #pragma unroll
    for (int m = 0; m < 32; m++) w[m] = Wp[(h * 32 + m) * CDIM + j];
    #pragma unroll
    for (int dd = 0; dd < 8; dd++) {
        int d = d0 + dd;
        float p = 0.f;
        #pragma unroll
        for (int m = 0; m < 32; m++) p += kvs[m * 32 + d] * w[m];
        g_P[((long)n * CDIM + h * 32 + d) * CDIM + j] = p;
    }
}

// ---------------------------------------------------------------------------
// k_z: z[row][h] = 1/(q[row, h*32:h*32+32] . ksum[n, h*32:+32] + eps).
//      One warp per row; head h = lane>>2 (4 lanes x 8 dims per head).
// ---------------------------------------------------------------------------
__global__ __launch_bounds__(256) void k_z()
{
    const int row  = blockIdx.x * 8 + (threadIdx.x >> 5);
    const int lane = threadIdx.x & 31;
    const int n = row / LB;
    const float* qr = g_q + (long)row * CDIM;
    const float* ks = g_ksum + n * CDIM;
    float4 a0 = *(const float4*)(qr + lane * 8);
    float4 a1 = *(const float4*)(qr + lane * 8 + 4);
    float4 k0 = *(const float4*)(ks + lane * 8);
    float4 k1 = *(const float4*)(ks + lane * 8 + 4);
    float s = a0.x*k0.x + a0.y*k0.y + a0.z*k0.z + a0.w*k0.w
            + a1.x*k1.x + a1.y*k1.y + a1.z*k1.z + a1.w*k1.w;
    // reduce within each 4-lane head group
    s += __shfl_xor_sync(0xffffffffu, s, 1);
    s += __shfl_xor_sync(0xffffffffu, s, 2);
    if ((lane & 3) == 0) g_z[row * HN + (lane >> 2)] = 1.f / (s + 1e-6f);
}

// ---------------------------------------------------------------------------
// k3: out = (z .* q) @ P_n + b_proj via TF32 MMA, double-buffered.
//     Grid 640, block 512, tile 128 x 256, warp grid 4x4 (32x64 each).
// ---------------------------------------------------------------------------
__device__ __forceinline__ void k3_loadA(unsigned* Ab, long mbase, int kb, int tid)
{
    const int h = kb >> 5;                     // this 32-chunk is one head
    #pragma unroll
    for (int it = 0; it < 2; ++it) {
        int idx = tid + it * 512;              // 0..1023
        int r = idx >> 3, c4 = idx & 7;
        float4 v = *(const float4*)(g_q + (mbase + r) * CDIM + kb + c4 * 4);
        float z = g_z[(mbase + r) * HN + h];
        uint4 u = { f2tf(v.x * z), f2tf(v.y * z), f2tf(v.z * z), f2tf(v.w * z) };
        *(uint4*)&Ab[r * 36 + c4 * 4] = u;
    }
}

__device__ __forceinline__ void k3_loadB(const float* __restrict__ Pn,
                                         unsigned* Bb, int kb, int tid)
{
    #pragma unroll
    for (int it = 0; it < 4; ++it) {
        int idx = tid + it * 512;              // 0..2047
        int r = idx >> 6, c4 = idx & 63;
        float4 v = *(const float4*)(Pn + (kb + r) * CDIM + c4 * 4);
        uint4 u = { f2tf(v.x), f2tf(v.y), f2tf(v.z), f2tf(v.w) };
        *(uint4*)&Bb[r * 264 + c4 * 4] = u;
    }
}

__global__ __launch_bounds__(512, 1) void k3_proj(const float* __restrict__ bp,
                                                  float* __restrict__ out)
{
    extern __shared__ float sm[];
    unsigned* As = (unsigned*)sm;               // 2 x [128][36]
    unsigned* Bs = (unsigned*)(sm + 9216);      // 2 x [32][264]

    const int tile = blockIdx.x;   // 0..639
    const int n    = tile / TILES;
    const float* Pn = g_P + (long)n * CDIM * CDIM;
    const int tid  = threadIdx.x;
    const int warp = tid >> 5, lane = tid & 31;
    const int wm = warp & 3, wn = warp >> 2;    // 4 x 4 warp grid
    const int rb = wm * 32, cb = wn * 64;       // warp tile 32 x 64
    const int g  = lane >> 2, tg = lane & 3;
    const long mbase = (long)tile * TM;

    float acc[2][8][4];
    #pragma unroll
    for (int mt = 0; mt < 2; mt++)
        #pragma unroll
        for (int nt = 0; nt < 8; nt++)
            #pragma unroll
            for (int e = 0; e < 4; e++) acc[mt][nt][e] = 0.f;

    k3_loadA(As, mbase, 0, tid);
    k3_loadB(Pn, Bs, 0, tid);
    __syncthreads();

    for (int i = 0; i < 8; i++) {
        int cur = i & 1;
        if (i < 7) {
            k3_loadA(As + (cur ^ 1) * 4608, mbase, (i + 1) * 32, tid);
            k3_loadB(Pn, Bs + (cur ^ 1) * 8448, (i + 1) * 32, tid);
        }
        unsigned* Ac = As + cur * 4608;
        unsigned* Bc = Bs + cur * 8448;
        #pragma unroll
        for (int ks = 0; ks < 32; ks += 8) {
            unsigned a[2][4], b[8][2];
            #pragma unroll
            for (int mt = 0; mt < 2; mt++) {
                int base = (rb + mt * 16 + g) * 36 + ks + tg;
                a[mt][0] = Ac[base];
                a[mt][1] = Ac[base + 8 * 36];
                a[mt][2] = Ac[base + 4];
                a[mt][3] = Ac[base + 8 * 36 + 4];
            }
            #pragma unroll
            for (int nt = 0; nt < 8; nt++) {
                int col = cb + nt * 8 + g;
                b[nt][0] = Bc[(ks + tg) * 264 + col];
                b[nt][1] = Bc[(ks + tg + 4) * 264 + col];
            }
            #pragma unroll
            for (int mt = 0; mt < 2; mt++)
                #pragma unroll
                for (int nt = 0; nt < 8; nt++)
                    mma_tf32(acc[mt][nt], a[mt], b[nt]);
        }
        __syncthreads();
    }

    #pragma unroll
    for (int mt = 0; mt < 2; mt++)
        #pragma unroll
        for (int nt = 0; nt < 8; nt++) {
            int c = cb + nt * 8 + tg * 2;
            float b0 = bp[c];
            float b1 = bp[c + 1];
            #pragma unroll
            for (int half = 0; half < 2; half++) {
                int r = rb + mt * 16 + g + half * 8;
                float2 o;
                o.x = acc[mt][nt][half * 2 + 0] + b0;
                o.y = acc[mt][nt][half * 2 + 1] + b1;
                *(float2*)(out + (mbase + r) * CDIM + c) = o;
            }
        }
}

// ---------------------------------------------------------------------------
extern "C" void kernel_launch(void* const* d_in, const int* in_sizes, int n_in,
                              void* d_out, int out_size)
{
    const float* x     = (const float*)d_in[0];
    const float* Wqkv  = (const float*)d_in[1];
    const float* Wproj = (const float*)d_in[2];
    const float* bproj = (const float*)d_in[3];
    float* out = (float*)d_out;

    cudaFuncSetAttribute(k1_qkv,  cudaFuncAttributeMaxDynamicSharedMemorySize, K1_TOT * 4);
    cudaFuncSetAttribute(k3_proj, cudaFuncAttributeMaxDynamicSharedMemorySize, 26112 * 4);

    k1_qkv<<<640, 512, K1_TOT * 4>>>(x, Wqkv);

    dim3 g2(NBATCH, HN);
    k_reduceP<<<g2, 1024>>>(Wproj);

    k_z<<<MROWS / 8, 256>>>();

    k3_proj<<<640, 512, 26112 * 4>>>(bproj, out);
}

// round 10
// speedup vs baseline: 1.2579x; 1.2579x over previous
#include <cuda_runtime.h>
#include <math.h>

// Problem constants
#define MROWS 81920          // BV*HW = 20*4096  (== B*L = 4*20480)
#define CDIM  256
#define LB    20480          // rows per batch n
#define HN    8
#define DH    32
#define NBATCH 4
#define TILES 160            // L-tiles of 128 per batch
#define TM 128
#define TK 32

// Scratch (static __device__ — no allocation allowed)
__device__ float g_q   [MROWS * CDIM];                  // elu(q)+1
__device__ float g_z   [MROWS * HN];                    // per-(row,head) 1/(q.ksum+eps)
__device__ float g_kvp [(long)640 * HN * DH * DH];      // per-tile kv partials
__device__ float g_ksp [(long)640 * HN * DH];           // per-tile k_sum partials
__device__ float g_ksum[NBATCH * CDIM];                 // [n][h*32+d]
__device__ float g_P   [NBATCH * CDIM * CDIM];          // P_n = kv^T @ W_proj

__device__ __forceinline__ unsigned f2tf(float f) {
    unsigned u;
    asm("cvt.rna.tf32.f32 %0, %1;" : "=r"(u) : "f"(f));
    return u;
}

__device__ __forceinline__ void mma_tf32(float* c, const unsigned* a, const unsigned* b) {
    asm volatile(
        "mma.sync.aligned.m16n8k8.row.col.f32.tf32.tf32.f32 "
        "{%0,%1,%2,%3}, {%4,%5,%6,%7}, {%8,%9}, {%0,%1,%2,%3};\n"
        : "+f"(c[0]), "+f"(c[1]), "+f"(c[2]), "+f"(c[3])
        : "r"(a[0]), "r"(a[1]), "r"(a[2]), "r"(a[3]), "r"(b[0]), "r"(b[1]));
}

// ---------------------------------------------------------------------------
// k1: per (head, L-tile of 128 rows): qkv GEMM slice (128 x 96) via TF32 MMA,
//     double-buffered; elu+1; q->g_q; kv via compensated TF32 MMA; ksum.
//     Grid (8, 640), 256 threads, occ 2.
// Smem (words): As 2x4608, Bs 2x3328 (=15872); epilogue planes overlap:
//     khi/vhi/klo/vlo 4x4224 (=16896), sc_ks 256. Total 17152 w = 68608 B.
// ---------------------------------------------------------------------------
__device__ __forceinline__ void k1_load(const float* __restrict__ x,
                                        const float* __restrict__ Wqkv,
                                        unsigned* Ab, unsigned* Bb,
                                        long mbase, int h, int kb, int tid)
{
    #pragma unroll
    for (int it = 0; it < 4; ++it) {
        int idx = tid + it * 256;              // 0..1023
        int r = idx >> 3, c4 = idx & 7;
        float4 v = *(const float4*)(x + (mbase + r) * CDIM + kb + c4 * 4);
        uint4 u = { f2tf(v.x), f2tf(v.y), f2tf(v.z), f2tf(v.w) };
        *(uint4*)&Ab[r * 36 + c4 * 4] = u;
    }
    #pragma unroll
    for (int it = 0; it < 3; ++it) {
        int idx = tid + it * 256;              // 0..767
        int r = idx / 24, c4 = idx % 24;
        int j = c4 * 4;
        int part = j >> 5, jj = j & 31;
        float4 v = *(const float4*)(Wqkv + (kb + r) * 768 + part * 256 + h * 32 + jj);
        uint4 u = { f2tf(v.x), f2tf(v.y), f2tf(v.z), f2tf(v.w) };
        *(uint4*)&Bb[r * 104 + j] = u;
    }
}

__global__ __launch_bounds__(256, 2) void k1_qkv(const float* __restrict__ x,
                                                 const float* __restrict__ Wqkv)
{
    extern __shared__ float sm[];
    unsigned* As = (unsigned*)sm;                   // 2 x [128][36]
    unsigned* Bs = (unsigned*)(sm + 9216);          // 2 x [32][104]
    // Epilogue overlays (used only after final GEMM sync):
    unsigned* khi = (unsigned*)sm;                  // [32][132] (d, l)
    unsigned* vhi = khi + 4224;
    unsigned* klo = vhi + 4224;
    unsigned* vlo = klo + 4224;
    float* sc_ks = sm + 16896;                      // 256 floats

    const int h    = blockIdx.x;        // 0..7
    const int tile = blockIdx.y;        // 0..639
    const int tid  = threadIdx.x;
    const int warp = tid >> 5, lane = tid & 31;
    const int wm = warp >> 1, wn = warp & 1;        // 4 x 2 warp grid
    const int rb = wm * 32, cb = wn * 48;           // warp tile 32 x 48
    const int g  = lane >> 2, tg = lane & 3;
    const long mbase = (long)tile * TM;

    float acc[2][6][4];
    #pragma unroll
    for (int mt = 0; mt < 2; mt++)
        #pragma unroll
        for (int nt = 0; nt < 6; nt++)
            #pragma unroll
            for (int e = 0; e < 4; e++) acc[mt][nt][e] = 0.f;

    k1_load(x, Wqkv, As, Bs, mbase, h, 0, tid);
    __syncthreads();

    for (int i = 0; i < 8; i++) {
        int cur = i & 1;
        if (i < 7)
            k1_load(x, Wqkv, As + (cur ^ 1) * 4608, Bs + (cur ^ 1) * 3328,
                    mbase, h, (i + 1) * TK, tid);
        unsigned* Ac = As + cur * 4608;
        unsigned* Bc = Bs + cur * 3328;
        #pragma unroll
        for (int ks = 0; ks < TK; ks += 8) {
            unsigned a[2][4], b[6][2];
            #pragma unroll
            for (int mt = 0; mt < 2; mt++) {
                int base = (rb + mt * 16 + g) * 36 + ks + tg;
                a[mt][0] = Ac[base];
                a[mt][1] = Ac[base + 8 * 36];
                a[mt][2] = Ac[base + 4];
                a[mt][3] = Ac[base + 8 * 36 + 4];
            }
            #pragma unroll
            for (int nt = 0; nt < 6; nt++) {
                int col = cb + nt * 8 + g;
                b[nt][0] = Bc[(ks + tg) * 104 + col];
                b[nt][1] = Bc[(ks + tg + 4) * 104 + col];
            }
            #pragma unroll
            for (int mt = 0; mt < 2; mt++)
                #pragma unroll
                for (int nt = 0; nt < 6; nt++)
                    mma_tf32(acc[mt][nt], a[mt], b[nt]);
        }
        __syncthreads();
    }

    // Epilogue: elu+1 on q,k; q -> global; k,v hi/lo planes (transposed, (d,l))
    #pragma unroll
    for (int mt = 0; mt < 2; mt++)
        #pragma unroll
        for (int nt = 0; nt < 6; nt++)
            #pragma unroll
            for (int e = 0; e < 4; e++) {
                int r = rb + mt * 16 + g + ((e >= 2) ? 8 : 0);
                int c = cb + nt * 8 + tg * 2 + (e & 1);
                float val = acc[mt][nt][e];
                int part = c >> 5, jj = c & 31;
                if (part == 0) {
                    val = (val > 0.f) ? (val + 1.f) : expf(val);
                    g_q[(mbase + r) * CDIM + h * 32 + jj] = val;
                } else if (part == 1) {
                    val = (val > 0.f) ? (val + 1.f) : expf(val);
                    unsigned hb = f2tf(val);
                    float hf = __uint_as_float(hb);
                    khi[jj * 132 + r] = hb;
                    klo[jj * 132 + r] = f2tf(val - hf);
                } else {
                    unsigned hb = f2tf(val);
                    float hf = __uint_as_float(hb);
                    vhi[jj * 132 + r] = hb;
                    vlo[jj * 132 + r] = f2tf(val - hf);
                }
            }
    __syncthreads();

    // kv[m][d] = sum_l v[l][m]*k[l][d] via compensated TF32 MMA.
    // 8 warps: warp = (mh, no); each covers m16 x d8 over all 128 l.
    {
        const int mh = warp & 1, no = warp >> 1;
        float c4v[4] = {0.f, 0.f, 0.f, 0.f};
        #pragma unroll
        for (int li = 0; li < 16; li++) {
            int l0 = li * 8;
            unsigned avh[4], avl[4], bkh[2], bkl[2];
            int ab = (mh * 16 + g) * 132 + l0 + tg;
            avh[0] = vhi[ab];            avh[1] = vhi[ab + 8 * 132];
            avh[2] = vhi[ab + 4];        avh[3] = vhi[ab + 8 * 132 + 4];
            avl[0] = vlo[ab];            avl[1] = vlo[ab + 8 * 132];
            avl[2] = vlo[ab + 4];        avl[3] = vlo[ab + 8 * 132 + 4];
            int bb = (no * 8 + g) * 132 + l0 + tg;
            bkh[0] = khi[bb];            bkh[1] = khi[bb + 4];
            bkl[0] = klo[bb];            bkl[1] = klo[bb + 4];
            mma_tf32(c4v, avh, bkh);
            mma_tf32(c4v, avh, bkl);
            mma_tf32(c4v, avl, bkh);
        }
        #pragma unroll
        for (int e = 0; e < 4; e++) {
            int m  = mh * 16 + g + ((e >= 2) ? 8 : 0);
            int d2 = no * 8 + tg * 2 + (e & 1);
            g_kvp[(long)(tile * HN + h) * 1024 + m * 32 + d2] = c4v[e];
        }

        // ksum partials: d = tid>>3 (0..31), cc = tid&7 (8 chunks of 16 l)
        {
            int d = tid >> 3, cc = tid & 7;
            float s = 0.f;
            #pragma unroll
            for (int l = cc * 16; l < cc * 16 + 16; l++)
                s += __uint_as_float(khi[d * 132 + l]) +
                     __uint_as_float(klo[d * 132 + l]);
            sc_ks[d * 8 + cc] = s;
        }
        __syncthreads();
        if (tid < 32) {
            float s2 = 0.f;
            #pragma unroll
            for (int c = 0; c < 8; c++) s2 += sc_ks[tid * 8 + c];
            g_ksp[(long)(tile * HN + h) * 32 + tid] = s2;
        }
    }
}

// ---------------------------------------------------------------------------
// k_reduceP: fixed-order reduction of kv/k_sum partials per (n,h), then
//            P[n][h*32+d][j] = sum_m kv[m][d] * Wp[h*32+m][j]  (fp32 exact)
// ---------------------------------------------------------------------------
__global__ __launch_bounds__(1024) void k_reduceP(const float* __restrict__ Wp)
{
    __shared__ float kvs[1024];
    const int n = blockIdx.x, h = blockIdx.y;
    const int tid = threadIdx.x;  // 0..1023 (= m*32+d)
    float s = 0.f;
    for (int t = 0; t < TILES; t++)
        s += g_kvp[((long)(n * TILES + t) * HN + h) * 1024 + tid];
    kvs[tid] = s;
    if (tid < 32) {
        float s2 = 0.f;
        for (int t = 0; t < TILES; t++)
            s2 += g_ksp[((long)(n * TILES + t) * HN + h) * 32 + tid];
        g_ksum[n * CDIM + h * 32 + tid] = s2;
    }
    __syncthreads();

    const int j  = tid & 255;
    const int d0 = (tid >> 8) * 8;
    float w[32];
    #pragma unroll
    for (int m = 0; m < 32; m++) w[m] = Wp[(h * 32 + m) * CDIM + j];
    #pragma unroll
    for (int dd = 0; dd < 8; dd++) {
        int d = d0 + dd;
        float p = 0.f;
        #pragma unroll
        for (int m = 0; m < 32; m++) p += kvs[m * 32 + d] * w[m];
        g_P[((long)n * CDIM + h * 32 + d) * CDIM + j] = p;
    }
}

// ---------------------------------------------------------------------------
// k_z: z[row][h] = 1/(q[row,h*32:+32] . ksum[n,h*32:+32] + eps).
//      One warp per row; head h = lane>>2 (4 lanes x 8 dims per head).
// ---------------------------------------------------------------------------
__global__ __launch_bounds__(256) void k_z()
{
    const int row  = blockIdx.x * 8 + (threadIdx.x >> 5);
    const int lane = threadIdx.x & 31;
    const int n = row / LB;
    const float* qr = g_q + (long)row * CDIM;
    const float* ks = g_ksum + n * CDIM;
    float4 a0 = *(const float4*)(qr + lane * 8);
    float4 a1 = *(const float4*)(qr + lane * 8 + 4);
    float4 k0 = *(const float4*)(ks + lane * 8);
    float4 k1 = *(const float4*)(ks + lane * 8 + 4);
    float s = a0.x*k0.x + a0.y*k0.y + a0.z*k0.z + a0.w*k0.w
            + a1.x*k1.x + a1.y*k1.y + a1.z*k1.z + a1.w*k1.w;
    s += __shfl_xor_sync(0xffffffffu, s, 1);
    s += __shfl_xor_sync(0xffffffffu, s, 2);
    if ((lane & 3) == 0) g_z[row * HN + (lane >> 2)] = 1.f / (s + 1e-6f);
}

// ---------------------------------------------------------------------------
// k3: out = (z .* q) @ P_n + b_proj via TF32 MMA, double-buffered.
//     Grid (640, 2), 256 threads, tile 128 x 128, warp grid 4x2 (32x64).
//     Smem: As 2x4608 + Bs 2x4352 = 17920 w = 71680 B, occ 2.
// ---------------------------------------------------------------------------
__device__ __forceinline__ void k3_loadA(unsigned* Ab, long mbase, int kb, int tid)
{
    const int h = kb >> 5;                     // this 32-chunk is one head
    #pragma unroll
    for (int it = 0; it < 4; ++it) {
        int idx = tid + it * 256;              // 0..1023
        int r = idx >> 3, c4 = idx & 7;
        float4 v = *(const float4*)(g_q + (mbase + r) * CDIM + kb + c4 * 4);
        float z = g_z[(mbase + r) * HN + h];
        uint4 u = { f2tf(v.x * z), f2tf(v.y * z), f2tf(v.z * z), f2tf(v.w * z) };
        *(uint4*)&Ab[r * 36 + c4 * 4] = u;
    }
}

__device__ __forceinline__ void k3_loadB(const float* __restrict__ Pn,
                                         unsigned* Bb, int nblk, int kb, int tid)
{
    #pragma unroll
    for (int it = 0; it < 4; ++it) {
        int idx = tid + it * 256;              // 0..1023
        int r = idx >> 5, c4 = idx & 31;       // 32 rows x 32 float4 = 128 cols
        float4 v = *(const float4*)(Pn + (kb + r) * CDIM + nblk * 128 + c4 * 4);
        uint4 u = { f2tf(v.x), f2tf(v.y), f2tf(v.z), f2tf(v.w) };
        *(uint4*)&Bb[r * 136 + c4 * 4] = u;
    }
}

__global__ __launch_bounds__(256, 2) void k3_proj(const float* __restrict__ bp,
                                                  float* __restrict__ out)
{
    extern __shared__ float sm[];
    unsigned* As = (unsigned*)sm;               // 2 x [128][36]
    unsigned* Bs = (unsigned*)(sm + 9216);      // 2 x [32][136]

    const int tile = blockIdx.x;   // 0..639
    const int nblk = blockIdx.y;   // 0..1
    const int n    = tile / TILES;
    const float* Pn = g_P + (long)n * CDIM * CDIM;
    const int tid  = threadIdx.x;
    const int warp = tid >> 5, lane = tid & 31;
    const int wm = warp >> 1, wn = warp & 1;    // 4 x 2 warp grid
    const int rb = wm * 32, cb = wn * 64;       // warp tile 32 x 64
    const int g  = lane >> 2, tg = lane & 3;
    const long mbase = (long)tile * TM;

    float acc[2][8][4];
    #pragma unroll
    for (int mt = 0; mt < 2; mt++)
        #pragma unroll
        for (int nt = 0; nt < 8; nt++)
            #pragma unroll
            for (int e = 0; e < 4; e++) acc[mt][nt][e] = 0.f;

    k3_loadA(As, mbase, 0, tid);
    k3_loadB(Pn, Bs, nblk, 0, tid);
    __syncthreads();

    for (int i = 0; i < 8; i++) {
        int cur = i & 1;
        if (i < 7) {
            k3_loadA(As + (cur ^ 1) * 4608, mbase, (i + 1) * TK, tid);
            k3_loadB(Pn, Bs + (cur ^ 1) * 4352, nblk, (i + 1) * TK, tid);
        }
        unsigned* Ac = As + cur * 4608;
        unsigned* Bc = Bs + cur * 4352;
        #pragma unroll
        for (int ks = 0; ks < TK; ks += 8) {
            unsigned a[2][4], b[8][2];
            #pragma unroll
            for (int mt = 0; mt < 2; mt++) {
                int base = (rb + mt * 16 + g) * 36 + ks + tg;
                a[mt][0] = Ac[base];
                a[mt][1] = Ac[base + 8 * 36];
                a[mt][2] = Ac[base + 4];
                a[mt][3] = Ac[base + 8 * 36 + 4];
            }
            #pragma unroll
            for (int nt = 0; nt < 8; nt++) {
                int col = cb + nt * 8 + g;
                b[nt][0] = Bc[(ks + tg) * 136 + col];
                b[nt][1] = Bc[(ks + tg + 4) * 136 + col];
            }
            #pragma unroll
            for (int mt = 0; mt < 2; mt++)
                #pragma unroll
                for (int nt = 0; nt < 8; nt++)
                    mma_tf32(acc[mt][nt], a[mt], b[nt]);
        }
        __syncthreads();
    }

    #pragma unroll
    for (int mt = 0; mt < 2; mt++)
        #pragma unroll
        for (int nt = 0; nt < 8; nt++) {
            int c = cb + nt * 8 + tg * 2;
            float b0 = bp[nblk * 128 + c];
            float b1 = bp[nblk * 128 + c + 1];
            #pragma unroll
            for (int half = 0; half < 2; half++) {
                int r = rb + mt * 16 + g + half * 8;
                float2 o;
                o.x = acc[mt][nt][half * 2 + 0] + b0;
                o.y = acc[mt][nt][half * 2 + 1] + b1;
                *(float2*)(out + (mbase + r) * CDIM + nblk * 128 + c) = o;
            }
        }
}

// ---------------------------------------------------------------------------
extern "C" void kernel_launch(void* const* d_in, const int* in_sizes, int n_in,
                              void* d_out, int out_size)
{
    const float* x     = (const float*)d_in[0];
    const float* Wqkv  = (const float*)d_in[1];
    const float* Wproj = (const float*)d_in[2];
    const float* bproj = (const float*)d_in[3];
    float* out = (float*)d_out;

    cudaFuncSetAttribute(k1_qkv,  cudaFuncAttributeMaxDynamicSharedMemorySize, 17152 * 4);
    cudaFuncSetAttribute(k3_proj, cudaFuncAttributeMaxDynamicSharedMemorySize, 17920 * 4);

    dim3 g1(HN, MROWS / TM);           // (8, 640)
    k1_qkv<<<g1, 256, 17152 * 4>>>(x, Wqkv);

    dim3 g2(NBATCH, HN);               // (4, 8)
    k_reduceP<<<g2, 1024>>>(Wproj);

    k_z<<<MROWS / 8, 256>>>();

    dim3 g3(MROWS / TM, 2);            // (640, 2)
    k3_proj<<<g3, 256, 17920 * 4>>>(bproj, out);
}

// round 12
// speedup vs baseline: 1.3753x; 1.0934x over previous
#include <cuda_runtime.h>
#include <math.h>

// Problem constants
#define MROWS 81920          // BV*HW = 20*4096  (== B*L = 4*20480)
#define CDIM  256
#define LB    20480          // rows per batch n
#define HN    8
#define DH    32
#define NBATCH 4
#define TILES 160            // L-tiles of 128 per batch
#define TM 128
#define TK 32

// Scratch (static __device__ — no allocation allowed)
__device__ float g_xt  [MROWS * CDIM];                  // tf32(x)
__device__ float g_wt  [CDIM * 768];                    // tf32(Wqkv)
__device__ float g_q   [MROWS * CDIM];                  // elu(q)+1 (fp32)
__device__ float g_qz  [MROWS * CDIM];                  // tf32(z*q)
__device__ float g_kvp [(long)640 * HN * DH * DH];      // per-tile kv partials
__device__ float g_ksp [(long)640 * HN * DH];           // per-tile k_sum partials
__device__ float g_ksum[NBATCH * CDIM];                 // [n][h*32+d]
__device__ float g_P   [NBATCH * CDIM * CDIM];          // tf32(kv^T @ W_proj)

__device__ __forceinline__ unsigned f2tf(float f) {
    unsigned u;
    asm("cvt.rna.tf32.f32 %0, %1;" : "=r"(u) : "f"(f));
    return u;
}

__device__ __forceinline__ void mma_tf32(float* c, const unsigned* a, const unsigned* b) {
    asm volatile(
        "mma.sync.aligned.m16n8k8.row.col.f32.tf32.tf32.f32 "
        "{%0,%1,%2,%3}, {%4,%5,%6,%7}, {%8,%9}, {%0,%1,%2,%3};\n"
        : "+f"(c[0]), "+f"(c[1]), "+f"(c[2]), "+f"(c[3])
        : "r"(a[0]), "r"(a[1]), "r"(a[2]), "r"(a[3]), "r"(b[0]), "r"(b[1]));
}

__device__ __forceinline__ void cpa16(unsigned dst, const void* src) {
    asm volatile("cp.async.cg.shared.global [%0], [%1], 16;" :: "r"(dst), "l"(src));
}
#define CP_COMMIT() asm volatile("cp.async.commit_group;")
#define CP_WAIT0()  asm volatile("cp.async.wait_group 0;")

// ---------------------------------------------------------------------------
// k_cvt: tf32-round x and Wqkv into g_xt / g_wt. 2584 blocks x 256 thr x 8 f4.
// ---------------------------------------------------------------------------
#define XF4 5242880L         // float4 count of x
__global__ __launch_bounds__(256) void k_cvt(const float* __restrict__ x,
                                             const float* __restrict__ W)
{
    #pragma unroll
    for (int it = 0; it < 8; ++it) {
        long i = (long)blockIdx.x * 2048 + it * 256 + threadIdx.x;
        float4 v; float* dst;
        if (i < XF4) {
            v = ((const float4*)x)[i];
            dst = g_xt + i * 4;
        } else {
            long j = i - XF4;                  // < 49152
            v = ((const float4*)W)[j];
            dst = g_wt + j * 4;
        }
        uint4 u = { f2tf(v.x), f2tf(v.y), f2tf(v.z), f2tf(v.w) };
        *(uint4*)dst = u;
    }
}

// ---------------------------------------------------------------------------
// k1: per (head, L-tile of 128 rows): qkv GEMM slice (128 x 96) via TF32 MMA,
//     cp.async double-buffered; elu+1; q staged->coalesced STG; kv via
//     compensated TF32 MMA; ksum. Grid (8, 640), 256 threads, occ 2.
// Smem (words): As 2x4608, Bs 2x3328 (=15872 GEMM);
//     overlays: khi/vhi/klo/vlo 4x4224 (=16896), qpl 4608 @16896,
//     sc_ks 256 @21504. Total 21760 w = 87040 B.
// ---------------------------------------------------------------------------
__device__ __forceinline__ void k1_load_async(unsigned Ab, unsigned Bb,
                                              long mbase, int h, int kb, int tid)
{
    #pragma unroll
    for (int it = 0; it < 4; ++it) {
        int idx = tid + it * 256;              // 0..1023
        int r = idx >> 3, c4 = idx & 7;
        cpa16(Ab + (r * 36 + c4 * 4) * 4, g_xt + (mbase + r) * CDIM + kb + c4 * 4);
    }
    #pragma unroll
    for (int it = 0; it < 3; ++it) {
        int idx = tid + it * 256;              // 0..767
        int r = idx / 24, c4 = idx % 24;
        int j = c4 * 4;
        int part = j >> 5, jj = j & 31;
        cpa16(Bb + (r * 104 + j) * 4, g_wt + (kb + r) * 768 + part * 256 + h * 32 + jj);
    }
}

__global__ __launch_bounds__(256, 2) void k1_qkv()
{
    extern __shared__ float sm[];
    unsigned* As = (unsigned*)sm;                   // 2 x [128][36]
    unsigned* Bs = (unsigned*)(sm + 9216);          // 2 x [32][104]
    // Epilogue overlays (used only after final GEMM sync):
    unsigned* khi = (unsigned*)sm;                  // [32][132] (d, l)
    unsigned* vhi = khi + 4224;
    unsigned* klo = vhi + 4224;
    unsigned* vlo = klo + 4224;
    float* qpl   = sm + 16896;                      // [128][36] fp32
    float* sc_ks = sm + 21504;                      // 256 floats
    const unsigned smu = (unsigned)__cvta_generic_to_shared(sm);

    const int h    = blockIdx.x;        // 0..7
    const int tile = blockIdx.y;        // 0..639
    const int tid  = threadIdx.x;
    const int warp = tid >> 5, lane = tid & 31;
    const int wm = warp >> 1, wn = warp & 1;        // 4 x 2 warp grid
    const int rb = wm * 32, cb = wn * 48;           // warp tile 32 x 48
    const int g  = lane >> 2, tg = lane & 3;
    const long mbase = (long)tile * TM;

    float acc[2][6][4];
    #pragma unroll
    for (int mt = 0; mt < 2; mt++)
        #pragma unroll
        for (int nt = 0; nt < 6; nt++)
            #pragma unroll
            for (int e = 0; e < 4; e++) acc[mt][nt][e] = 0.f;

    k1_load_async(smu, smu + 9216 * 4, mbase, h, 0, tid);
    CP_COMMIT(); CP_WAIT0();
    __syncthreads();

    for (int i = 0; i < 8; i++) {
        int cur = i & 1;
        if (i < 7) {
            k1_load_async(smu + (cur ^ 1) * 4608 * 4,
                          smu + (9216 + (cur ^ 1) * 3328) * 4,
                          mbase, h, (i + 1) * TK, tid);
            CP_COMMIT();
        }
        unsigned* Ac = As + cur * 4608;
        unsigned* Bc = Bs + cur * 3328;
        #pragma unroll
        for (int ks = 0; ks < TK; ks += 8) {
            unsigned a[2][4], b[6][2];
            #pragma unroll
            for (int mt = 0; mt < 2; mt++) {
                int base = (rb + mt * 16 + g) * 36 + ks + tg;
                a[mt][0] = Ac[base];
                a[mt][1] = Ac[base + 8 * 36];
                a[mt][2] = Ac[base + 4];
                a[mt][3] = Ac[base + 8 * 36 + 4];
            }
            #pragma unroll
            for (int nt = 0; nt < 6; nt++) {
                int col = cb + nt * 8 + g;
                b[nt][0] = Bc[(ks + tg) * 104 + col];
                b[nt][1] = Bc[(ks + tg + 4) * 104 + col];
            }
            #pragma unroll
            for (int mt = 0; mt < 2; mt++)
                #pragma unroll
                for (int nt = 0; nt < 6; nt++)
                    mma_tf32(acc[mt][nt], a[mt], b[nt]);
        }
        if (i < 7) CP_WAIT0();
        __syncthreads();
    }

    // Epilogue: elu+1 on q,k; q -> qpl plane; k,v hi/lo planes (d,l)
    #pragma unroll
    for (int mt = 0; mt < 2; mt++)
        #pragma unroll
        for (int nt = 0; nt < 6; nt++)
            #pragma unroll
            for (int e = 0; e < 4; e++) {
                int r = rb + mt * 16 + g + ((e >= 2) ? 8 : 0);
                int c = cb + nt * 8 + tg * 2 + (e & 1);
                float val = acc[mt][nt][e];
                int part = c >> 5, jj = c & 31;
                if (part == 0) {
                    val = (val > 0.f) ? (val + 1.f) : expf(val);
                    qpl[r * 36 + jj] = val;
                } else if (part == 1) {
                    val = (val > 0.f) ? (val + 1.f) : expf(val);
                    unsigned hb = f2tf(val);
                    float hf = __uint_as_float(hb);
                    khi[jj * 132 + r] = hb;
                    klo[jj * 132 + r] = f2tf(val - hf);
                } else {
                    unsigned hb = f2tf(val);
                    float hf = __uint_as_float(hb);
                    vhi[jj * 132 + r] = hb;
                    vlo[jj * 132 + r] = f2tf(val - hf);
                }
            }
    __syncthreads();

    // Coalesced q store: 128 rows x 8 float4
    #pragma unroll
    for (int it = 0; it < 4; ++it) {
        int idx = tid + it * 256;              // 0..1023
        int r = idx >> 3, c4 = idx & 7;
        float4 v = *(const float4*)&qpl[r * 36 + c4 * 4];
        *(float4*)(g_q + (mbase + r) * CDIM + h * 32 + c4 * 4) = v;
    }

    // kv[m][d] = sum_l v[l][m]*k[l][d] via compensated TF32 MMA.
    // 8 warps: warp = (mh, no); each covers m16 x d8 over all 128 l.
    {
        const int mh = warp & 1, no = warp >> 1;
        float c4v[4] = {0.f, 0.f, 0.f, 0.f};
        #pragma unroll
        for (int li = 0; li < 16; li++) {
            int l0 = li * 8;
            unsigned avh[4], avl[4], bkh[2], bkl[2];
            int ab = (mh * 16 + g) * 132 + l0 + tg;
            avh[0] = vhi[ab];            avh[1] = vhi[ab + 8 * 132];
            avh[2] = vhi[ab + 4];        avh[3] = vhi[ab + 8 * 132 + 4];
            avl[0] = vlo[ab];            avl[1] = vlo[ab + 8 * 132];
            avl[2] = vlo[ab + 4];        avl[3] = vlo[ab + 8 * 132 + 4];
            int bb = (no * 8 + g) * 132 + l0 + tg;
            bkh[0] = khi[bb];            bkh[1] = khi[bb + 4];
            bkl[0] = klo[bb];            bkl[1] = klo[bb + 4];
            mma_tf32(c4v, avh, bkh);
            mma_tf32(c4v, avh, bkl);
            mma_tf32(c4v, avl, bkh);
        }
        #pragma unroll
        for (int e = 0; e < 4; e++) {
            int m  = mh * 16 + g + ((e >= 2) ? 8 : 0);
            int d2 = no * 8 + tg * 2 + (e & 1);
            g_kvp[(long)(tile * HN + h) * 1024 + m * 32 + d2] = c4v[e];
        }

        // ksum partials: d = tid>>3 (0..31), cc = tid&7 (8 chunks of 16 l)
        {
            int d = tid >> 3, cc = tid & 7;
            float s = 0.f;
            #pragma unroll
            for (int l = cc * 16; l < cc * 16 + 16; l++)
                s += __uint_as_float(khi[d * 132 + l]) +
                     __uint_as_float(klo[d * 132 + l]);
            sc_ks[d * 8 + cc] = s;
        }
        __syncthreads();
        if (tid < 32) {
            float s2 = 0.f;
            #pragma unroll
            for (int c = 0; c < 8; c++) s2 += sc_ks[tid * 8 + c];
            g_ksp[(long)(tile * HN + h) * 32 + tid] = s2;
        }
    }
}

// ---------------------------------------------------------------------------
// k_reduceP: fixed-order reduction of kv/k_sum partials per (n,h), then
//            P[n][h*32+d][j] = tf32( sum_m kv[m][d] * Wp[h*32+m][j] )
// ---------------------------------------------------------------------------
__global__ __launch_bounds__(1024) void k_reduceP(const float* __restrict__ Wp)
{
    __shared__ float kvs[1024];
    const int n = blockIdx.x, h = blockIdx.y;
    const int tid = threadIdx.x;  // 0..1023 (= m*32+d)
    float s = 0.f;
    for (int t = 0; t < TILES; t++)
        s += g_kvp[((long)(n * TILES + t) * HN + h) * 1024 + tid];
    kvs[tid] = s;
    if (tid < 32) {
        float s2 = 0.f;
        for (int t = 0; t < TILES; t++)
            s2 += g_ksp[((long)(n * TILES + t) * HN + h) * 32 + tid];
        g_ksum[n * CDIM + h * 32 + tid] = s2;
    }
    __syncthreads();

    const int j  = tid & 255;
    const int d0 = (tid >> 8) * 8;
    float w[32];
    #pragma unroll
    for (int m = 0; m < 32; m++) w[m] = Wp[(h * 32 + m) * CDIM + j];
    #pragma unroll
    for (int dd = 0; dd < 8; dd++) {
        int d = d0 + dd;
        float p = 0.f;
        #pragma unroll
        for (int m = 0; m < 32; m++) p += kvs[m * 32 + d] * w[m];
        g_P[((long)n * CDIM + h * 32 + d) * CDIM + j] = __uint_as_float(f2tf(p));
    }
}

// ---------------------------------------------------------------------------
// k_qz: per (row,head): z = 1/(q.ksum + eps); g_qz = tf32(z*q).
//       One warp per row; head h = lane>>2 (4 lanes x 8 dims per head).
// ---------------------------------------------------------------------------
__global__ __launch_bounds__(256) void k_qz()
{
    const int row  = blockIdx.x * 8 + (threadIdx.x >> 5);
    const int lane = threadIdx.x & 31;
    const int n = row / LB;
    const float* qr = g_q + (long)row * CDIM;
    const float* ks = g_ksum + n * CDIM;
    float4 a0 = *(const float4*)(qr + lane * 8);
    float4 a1 = *(const float4*)(qr + lane * 8 + 4);
    float4 k0 = *(const float4*)(ks + lane * 8);
    float4 k1 = *(const float4*)(ks + lane * 8 + 4);
    float s = a0.x*k0.x + a0.y*k0.y + a0.z*k0.z + a0.w*k0.w
            + a1.x*k1.x + a1.y*k1.y + a1.z*k1.z + a1.w*k1.w;
    s += __shfl_xor_sync(0xffffffffu, s, 1);
    s += __shfl_xor_sync(0xffffffffu, s, 2);
    const float z = 1.f / (s + 1e-6f);
    uint4 u0 = { f2tf(a0.x*z), f2tf(a0.y*z), f2tf(a0.z*z), f2tf(a0.w*z) };
    uint4 u1 = { f2tf(a1.x*z), f2tf(a1.y*z), f2tf(a1.z*z), f2tf(a1.w*z) };
    *(uint4*)(g_qz + (long)row * CDIM + lane * 8)     = u0;
    *(uint4*)(g_qz + (long)row * CDIM + lane * 8 + 4) = u1;
}

// ---------------------------------------------------------------------------
// k3: out = qz @ P_n + b_proj via TF32 MMA, cp.async double-buffered.
//     Grid (640, 2), 256 threads, tile 128 x 128, warp grid 4x2 (32x64).
//     Smem: As 2x4608 + Bs 2x4352 = 17920 w = 71680 B, occ 2.
// ---------------------------------------------------------------------------
__device__ __forceinline__ void k3_load_async(unsigned Ab, unsigned Bb,
                                              const float* __restrict__ Pn,
                                              long mbase, int nblk, int kb, int tid)
{
    #pragma unroll
    for (int it = 0; it < 4; ++it) {
        int idx = tid + it * 256;              // 0..1023
        int r = idx >> 3, c4 = idx & 7;
        cpa16(Ab + (r * 36 + c4 * 4) * 4, g_qz + (mbase + r) * CDIM + kb + c4 * 4);
    }
    #pragma unroll
    for (int it = 0; it < 4; ++it) {
        int idx = tid + it * 256;              // 0..1023
        int r = idx >> 5, c4 = idx & 31;
        cpa16(Bb + (r * 136 + c4 * 4) * 4, Pn + (kb + r) * CDIM + nblk * 128 + c4 * 4);
    }
}

__global__ __launch_bounds__(256, 2) void k3_proj(const float* __restrict__ bp,
                                                  float* __restrict__ out)
{
    extern __shared__ float sm[];
    unsigned* As = (unsigned*)sm;               // 2 x [128][36]
    unsigned* Bs = (unsigned*)(sm + 9216);      // 2 x [32][136]
    const unsigned smu = (unsigned)__cvta_generic_to_shared(sm);

    const int tile = blockIdx.x;   // 0..639
    const int nblk = blockIdx.y;   // 0..1
    const int n    = tile / TILES;
    const float* Pn = g_P + (long)n * CDIM * CDIM;
    const int tid  = threadIdx.x;
    const int warp = tid >> 5, lane = tid & 31;
    const int wm = warp >> 1, wn = warp & 1;    // 4 x 2 warp grid
    const int rb = wm * 32, cb = wn * 64;       // warp tile 32 x 64
    const int g  = lane >> 2, tg = lane & 3;
    const long mbase = (long)tile * TM;

    float acc[2][8][4];
    #pragma unroll
    for (int mt = 0; mt < 2; mt++)
        #pragma unroll
        for (int nt = 0; nt < 8; nt++)
            #pragma unroll
            for (int e = 0; e < 4; e++) acc[mt][nt][e] = 0.f;

    k3_load_async(smu, smu + 9216 * 4, Pn, mbase, nblk, 0, tid);
    CP_COMMIT(); CP_WAIT0();
    __syncthreads();

    for (int i = 0; i < 8; i++) {
        int cur = i & 1;
        if (i < 7) {
            k3_load_async(smu + (cur ^ 1) * 4608 * 4,
                          smu + (9216 + (cur ^ 1) * 4352) * 4,
                          Pn, mbase, nblk, (i + 1) * TK, tid);
            CP_COMMIT();
        }
        unsigned* Ac = As + cur * 4608;
        unsigned* Bc = Bs + cur * 4352;
        #pragma unroll
        for (int ks = 0; ks < TK; ks += 8) {
            unsigned a[2][4], b[8][2];
            #pragma unroll
            for (int mt = 0; mt < 2; mt++) {
                int base = (rb + mt * 16 + g) * 36 + ks + tg;
                a[mt][0] = Ac[base];
                a[mt][1] = Ac[base + 8 * 36];
                a[mt][2] = Ac[base + 4];
                a[mt][3] = Ac[base + 8 * 36 + 4];
            }
            #pragma unroll
            for (int nt = 0; nt < 8; nt++) {
                int col = cb + nt * 8 + g;
                b[nt][0] = Bc[(ks + tg) * 136 + col];
                b[nt][1] = Bc[(ks + tg + 4) * 136 + col];
            }
            #pragma unroll
            for (int mt = 0; mt < 2; mt++)
                #pragma unroll
                for (int nt = 0; nt < 8; nt++)
                    mma_tf32(acc[mt][nt], a[mt], b[nt]);
        }
        if (i < 7) CP_WAIT0();
        __syncthreads();
    }

    #pragma unroll
    for (int mt = 0; mt < 2; mt++)
        #pragma unroll
        for (int nt = 0; nt < 8; nt++) {
            int c = cb + nt * 8 + tg * 2;
            float b0 = bp[nblk * 128 + c];
            float b1 = bp[nblk * 128 + c + 1];
            #pragma unroll
            for (int half = 0; half < 2; half++) {
                int r = rb + mt * 16 + g + half * 8;
                float2 o;
                o.x = acc[mt][nt][half * 2 + 0] + b0;
                o.y = acc[mt][nt][half * 2 + 1] + b1;
                *(float2*)(out + (mbase + r) * CDIM + nblk * 128 + c) = o;
            }
        }
}

// ---------------------------------------------------------------------------
extern "C" void kernel_launch(void* const* d_in, const int* in_sizes, int n_in,
                              void* d_out, int out_size)
{
    const float* x     = (const float*)d_in[0];
    const float* Wqkv  = (const float*)d_in[1];
    const float* Wproj = (const float*)d_in[2];
    const float* bproj = (const float*)d_in[3];
    float* out = (float*)d_out;

    cudaFuncSetAttribute(k1_qkv,  cudaFuncAttributeMaxDynamicSharedMemorySize, 21760 * 4);
    cudaFuncSetAttribute(k3_proj, cudaFuncAttributeMaxDynamicSharedMemorySize, 17920 * 4);

    k_cvt<<<2584, 256>>>(x, Wqkv);

    dim3 g1(HN, MROWS / TM);           // (8, 640)
    k1_qkv<<<g1, 256, 21760 * 4>>>();

    dim3 g2(NBATCH, HN);               // (4, 8)
    k_reduceP<<<g2, 1024>>>(Wproj);

    k_qz<<<MROWS / 8, 256>>>();

    dim3 g3(MROWS / TM, 2);            // (640, 2)
    k3_proj<<<g3, 256, 17920 * 4>>>(bproj, out);
}